// round 13
// baseline (speedup 1.0000x reference)
#include <cuda_runtime.h>
#include <cuda_bf16.h>
#include <cstdint>
#include <math.h>

#define LSEQ 2048
#define DMODEL 2048
#define QKVDIM 3072
#define HQ 16
#define HKV 4
#define HD 128

// ---------------- device scratch (no allocation allowed) ----------------
__device__ __align__(16) __nv_bfloat16 g_xhi[(size_t)LSEQ * DMODEL];
__device__ __align__(16) __nv_bfloat16 g_xlo[(size_t)LSEQ * DMODEL];
__device__ __align__(16) float g_proj[(size_t)LSEQ * QKVDIM];
__device__ __align__(16) __nv_bfloat16 g_Qhi[(size_t)HQ * LSEQ * HD];
__device__ __align__(16) __nv_bfloat16 g_Qlo[(size_t)HQ * LSEQ * HD];
__device__ __align__(16) __nv_bfloat16 g_Khi[(size_t)HKV * LSEQ * HD];
__device__ __align__(16) __nv_bfloat16 g_Klo[(size_t)HKV * LSEQ * HD];
__device__ __align__(16) __nv_bfloat16 g_VThi[(size_t)HKV * HD * LSEQ];
__device__ __align__(16) __nv_bfloat16 g_VTlo[(size_t)HKV * HD * LSEQ];
__device__ __align__(16) __nv_bfloat16 g_WqkvT_hi[(size_t)QKVDIM * DMODEL];
__device__ __align__(16) __nv_bfloat16 g_WqkvT_lo[(size_t)QKVDIM * DMODEL];
__device__ __align__(16) __nv_bfloat16 g_WoT_hi[(size_t)DMODEL * DMODEL];
__device__ __align__(16) __nv_bfloat16 g_WoT_lo[(size_t)DMODEL * DMODEL];
__device__ __align__(16) float g_S[(size_t)HQ * LSEQ * LSEQ];        // 268 MB
__device__ __align__(16) __nv_bfloat16 g_Shi[(size_t)HQ * LSEQ * LSEQ];
__device__ __align__(16) __nv_bfloat16 g_Slo[(size_t)HQ * LSEQ * LSEQ];
__device__ __align__(16) __nv_bfloat16 g_AOhi[(size_t)LSEQ * DMODEL];
__device__ __align__(16) __nv_bfloat16 g_AOlo[(size_t)LSEQ * DMODEL];

// ---------------- helpers ----------------
__device__ __forceinline__ uint32_t smem_u32(const void* p) {
    uint32_t a;
    asm("{ .reg .u64 t; cvta.to.shared.u64 t, %1; cvt.u32.u64 %0, t; }" : "=r"(a) : "l"(p));
    return a;
}
__device__ __forceinline__ void cp16(uint32_t dst, const void* src) {
    asm volatile("cp.async.cg.shared.global [%0], [%1], 16;" :: "r"(dst), "l"(src) : "memory");
}
#define CP_COMMIT() asm volatile("cp.async.commit_group;" ::: "memory")
#define CP_WAIT1()  asm volatile("cp.async.wait_group 1;" ::: "memory")
__device__ __forceinline__ void ldm_x4(uint32_t* r, uint32_t addr) {
    asm volatile("ldmatrix.sync.aligned.m8n8.x4.shared.b16 {%0,%1,%2,%3}, [%4];"
        : "=r"(r[0]), "=r"(r[1]), "=r"(r[2]), "=r"(r[3]) : "r"(addr));
}
__device__ __forceinline__ void mma16816(float* c, const uint32_t* a, const uint32_t* b) {
    asm volatile(
        "mma.sync.aligned.m16n8k16.row.col.f32.bf16.bf16.f32 "
        "{%0,%1,%2,%3}, {%4,%5,%6,%7}, {%8,%9}, {%0,%1,%2,%3};"
        : "+f"(c[0]), "+f"(c[1]), "+f"(c[2]), "+f"(c[3])
        : "r"(a[0]), "r"(a[1]), "r"(a[2]), "r"(a[3]), "r"(b[0]), "r"(b[1]));
}

// ---------------- HMMA GEMM ----------------
// C[M,N] = Ahi/lo[M,K] * (Bhi/lo[N,K])^T  with 3-pass bf16 split (fp32 accuracy).
// Block tile 128x128, BK=32, 256 threads (8 warps, warp tile 64x32), 2 CTAs/SM.
// SW128 swizzled smem rows of 128B: [hi 4x16B | lo 4x16B] per row. No padding.
// Stage = A(16KB) + B(16KB) = 32KB. 3 stages = 96KB -> 2 CTAs/SM (192KB).
#define STAGEB 32768
#define GSMEM (3 * STAGEB)

__device__ __forceinline__ void issue_tiles(
    uint32_t sb, int stage,
    const __nv_bfloat16* Ahi, const __nv_bfloat16* Alo,
    const __nv_bfloat16* Bhi, const __nv_bfloat16* Blo,
    int m0, int n0, int k0, int lda, int ldb, int tid)
{
    const uint32_t sbase = sb + (unsigned)stage * STAGEB;
#pragma unroll
    for (int i = 0; i < 4; i++) {
        const int idx = i * 256 + tid;
        const int r = idx >> 3;
        const int c = idx & 7;                       // 0-3: hi, 4-7: lo
        const int ke = (c & 3) * 8;
        const uint32_t dst = sbase + (unsigned)(r * 128 + ((c ^ (r & 7)) << 4));
        const __nv_bfloat16* srcA = (c < 4 ? Ahi : Alo) + (long)(m0 + r) * lda + k0 + ke;
        const __nv_bfloat16* srcB = (c < 4 ? Bhi : Blo) + (long)(n0 + r) * ldb + k0 + ke;
        cp16(dst, srcA);
        cp16(dst + 16384, srcB);
    }
}

// EPI=0: write fp32 C.  EPI=1: write bf16 hi/lo pair (Chi/Clo).
template <int EPI>
__global__ __launch_bounds__(256, 2)
void gemm_mma(const __nv_bfloat16* __restrict__ Ahi, const __nv_bfloat16* __restrict__ Alo,
              const __nv_bfloat16* __restrict__ Bhi, const __nv_bfloat16* __restrict__ Blo,
              float* __restrict__ C, __nv_bfloat16* __restrict__ Chi, __nv_bfloat16* __restrict__ Clo,
              int K, int lda, int ldb, int ldc,
              long aStr, long bStr, int bDiv, long cStr)
{
    extern __shared__ char smem[];
    const uint32_t sb = smem_u32(smem);
    const int tid = threadIdx.x;
    const int warp = tid >> 5;
    const int lane = tid & 31;
    const int wm = warp & 1;          // 2 warp rows (64 each)
    const int wn = warp >> 1;         // 4 warp cols (32 each)
    const int gid = lane >> 2;        // 0..7
    const int tg = lane & 3;          // 0..3
    const int z = blockIdx.z;

    Ahi += (long)z * aStr; Alo += (long)z * aStr;
    Bhi += (long)(z / bDiv) * bStr; Blo += (long)(z / bDiv) * bStr;

    const int m0 = blockIdx.y * 128;
    const int n0 = blockIdx.x * 128;

    // ldmatrix lane addressing. Row offsets (wm*64, mf*16, wn*32, nfp*16, +8) are
    // multiples of 8, so the SW128 XOR term is just (lane & 7) for every load.
    const int lx = lane & 7;
    // A: lanes 0-7 rows+0 kLo8 | 8-15 rows+8 kLo8 | 16-23 rows+0 kHi8 | 24-31 rows+8 kHi8
    const uint32_t arowoff = (unsigned)(wm * 64 + lx + ((lane >> 3) & 1) * 8) * 128;
    const int asel = lane >> 4;              // k-half chunk within ks
    // B: lanes 0-7 rows+0 kLo8 | 8-15 rows+0 kHi8 | 16-23 rows+8 kLo8 | 24-31 rows+8 kHi8
    const uint32_t browoff = (unsigned)(wn * 32 + lx + ((lane >> 4) & 1) * 8) * 128;
    const int bsel = (lane >> 3) & 1;

    float acc[4][4][4];
#pragma unroll
    for (int i = 0; i < 4; i++)
#pragma unroll
        for (int j = 0; j < 4; j++)
#pragma unroll
            for (int v = 0; v < 4; v++) acc[i][j][v] = 0.f;

    const int nch = K >> 5;
    issue_tiles(sb, 0, Ahi, Alo, Bhi, Blo, m0, n0, 0, lda, ldb, tid);
    CP_COMMIT();
    issue_tiles(sb, 1, Ahi, Alo, Bhi, Blo, m0, n0, 32, lda, ldb, tid);
    CP_COMMIT();

    int stage = 0, nstage = 2;
    for (int ch = 0; ch < nch; ch++) {
        CP_WAIT1();            // group ch complete (per-thread)
        __syncthreads();       // copies visible to all; all warps past compute(ch-1)
        if (ch + 2 < nch)
            issue_tiles(sb, nstage, Ahi, Alo, Bhi, Blo, m0, n0, (ch + 2) << 5, lda, ldb, tid);
        CP_COMMIT();           // empty group ok — keeps wait-count arithmetic valid

        const uint32_t sA = sb + (unsigned)stage * STAGEB;
        const uint32_t sB = sA + 16384;
#pragma unroll
        for (int ks = 0; ks < 2; ks++) {
            const uint32_t achi = (unsigned)(((ks * 2 + asel) ^ lx) << 4);
            const uint32_t aclo = (unsigned)(((ks * 2 + asel + 4) ^ lx) << 4);
            const uint32_t bchi = (unsigned)(((ks * 2 + bsel) ^ lx) << 4);
            const uint32_t bclo = (unsigned)(((ks * 2 + bsel + 4) ^ lx) << 4);
            uint32_t ahi[4][4], alo[4][4];
#pragma unroll
            for (int mf = 0; mf < 4; mf++) {
                const uint32_t ar = sA + arowoff + (unsigned)(mf * 16) * 128;
                ldm_x4(ahi[mf], ar + achi);
                ldm_x4(alo[mf], ar + aclo);
            }
#pragma unroll
            for (int nfp = 0; nfp < 2; nfp++) {
                uint32_t bh[4], bl[4];
                const uint32_t br = sB + browoff + (unsigned)(nfp * 16) * 128;
                ldm_x4(bh, br + bchi);
                ldm_x4(bl, br + bclo);
#pragma unroll
                for (int mf = 0; mf < 4; mf++) {
                    mma16816(acc[mf][nfp * 2 + 0], ahi[mf], bh + 0);
                    mma16816(acc[mf][nfp * 2 + 0], ahi[mf], bl + 0);
                    mma16816(acc[mf][nfp * 2 + 0], alo[mf], bh + 0);
                    mma16816(acc[mf][nfp * 2 + 1], ahi[mf], bh + 2);
                    mma16816(acc[mf][nfp * 2 + 1], ahi[mf], bl + 2);
                    mma16816(acc[mf][nfp * 2 + 1], alo[mf], bh + 2);
                }
            }
        }
        stage = (stage == 2) ? 0 : stage + 1;
        nstage = (nstage == 2) ? 0 : nstage + 1;
    }

    // ---- epilogue ----
#pragma unroll
    for (int mf = 0; mf < 4; mf++) {
#pragma unroll
        for (int nf = 0; nf < 4; nf++) {
            const int r = m0 + wm * 64 + mf * 16 + gid;
            const int cc = n0 + wn * 32 + nf * 8 + tg * 2;
#pragma unroll
            for (int half = 0; half < 2; half++) {
                const long off = (long)(r + half * 8) * ldc + cc;
                const float v0 = acc[mf][nf][half * 2 + 0];
                const float v1 = acc[mf][nf][half * 2 + 1];
                if (EPI == 0) {
                    float2 o; o.x = v0; o.y = v1;
                    *(float2*)(C + (long)z * cStr + off) = o;
                } else {
                    const __nv_bfloat16 h0 = __float2bfloat16(v0);
                    const __nv_bfloat16 h1 = __float2bfloat16(v1);
                    __nv_bfloat162 hp, lp;
                    hp.x = h0; hp.y = h1;
                    lp.x = __float2bfloat16(v0 - __bfloat162float(h0));
                    lp.y = __float2bfloat16(v1 - __bfloat162float(h1));
                    *(__nv_bfloat162*)(Chi + (long)z * cStr + off) = hp;
                    *(__nv_bfloat162*)(Clo + (long)z * cStr + off) = lp;
                }
            }
        }
    }
}

// ---------------- fp32 -> bf16 hi/lo split (elementwise, vectorized) ----------------
__global__ __launch_bounds__(256)
void split_kernel(const float* __restrict__ in, __nv_bfloat16* __restrict__ oh,
                  __nv_bfloat16* __restrict__ ol, int n4)
{
    const int i = blockIdx.x * 256 + threadIdx.x;
    if (i >= n4) return;
    const float4 v = ((const float4*)in)[i];
    const float* e = (const float*)&v;
    __nv_bfloat16 h[4], l[4];
#pragma unroll
    for (int j = 0; j < 4; j++) {
        h[j] = __float2bfloat16(e[j]);
        l[j] = __float2bfloat16(e[j] - __bfloat162float(h[j]));
    }
    ((uint2*)oh)[i] = *(uint2*)h;
    ((uint2*)ol)[i] = *(uint2*)l;
}

// ---------------- transpose + split ----------------
__global__ __launch_bounds__(256)
void transpose_convert(const float* __restrict__ in,
                       __nv_bfloat16* __restrict__ oh, __nv_bfloat16* __restrict__ ol,
                       int ldi, int ldo, long inStr, long outStr)
{
    const int z = blockIdx.z;
    in += (long)z * inStr;
    oh += (long)z * outStr;
    ol += (long)z * outStr;
    __shared__ float tb[32][33];
    const int n0 = blockIdx.x * 32, k0 = blockIdx.y * 32;
    const int tx = threadIdx.x & 31, ty = threadIdx.x >> 5;
#pragma unroll
    for (int i = 0; i < 4; i++)
        tb[ty + i * 8][tx] = in[(long)(k0 + ty + i * 8) * ldi + n0 + tx];
    __syncthreads();
#pragma unroll
    for (int i = 0; i < 4; i++) {
        const int n = ty + i * 8;
        const float v = tb[tx][n];
        const __nv_bfloat16 h = __float2bfloat16(v);
        const long o = (long)(n0 + n) * ldo + k0 + tx;
        oh[o] = h;
        ol[o] = __float2bfloat16(v - __bfloat162float(h));
    }
}

// ---------------- RoPE + split: Q and K to bf16 hi/lo ----------------
__global__ __launch_bounds__(256)
void rope_split_kernel()
{
    const int l = blockIdx.x;
    const float* pr = g_proj + (long)l * QKVDIM;

    for (int p = threadIdx.x; p < 20 * 64; p += blockDim.x) {
        const int head = p >> 6;
        const int d = p & 63;
        float c, s;
        if (d < 32) {
            const float f = exp2f(-10.0f * (float)d * (1.0f / 31.0f));
            sincosf((float)l * f, &s, &c);
        } else { c = 1.f; s = 0.f; }
        float x1, x2;
        __nv_bfloat16 *dh, *dl;
        long base;
        if (head < HQ) {
            x1 = pr[head * HD + d];
            x2 = pr[head * HD + d + 64];
            base = ((long)head * LSEQ + l) * HD;
            dh = g_Qhi; dl = g_Qlo;
        } else {
            const int kh = head - HQ;
            x1 = pr[HQ * HD + kh * HD + d];
            x2 = pr[HQ * HD + kh * HD + d + 64];
            base = ((long)kh * LSEQ + l) * HD;
            dh = g_Khi; dl = g_Klo;
        }
        const float r0 = x1 * c + x2 * s;
        const float r1 = -x1 * s + x2 * c;
        const __nv_bfloat16 h0 = __float2bfloat16(r0);
        const __nv_bfloat16 h1 = __float2bfloat16(r1);
        dh[base + d] = h0;
        dh[base + d + 64] = h1;
        dl[base + d] = __float2bfloat16(r0 - __bfloat162float(h0));
        dl[base + d + 64] = __float2bfloat16(r1 - __bfloat162float(h1));
    }
}

// ---------------- masked softmax with sink -> bf16 hi/lo ----------------
// FAITHFUL quirk: -inf where (q >= k && q < k+1024). Sink in denominator only.
__global__ __launch_bounds__(256)
void softmax_kernel(const float* __restrict__ sink)
{
    const int q = blockIdx.x;
    const int h = blockIdx.y;
    const size_t base = ((size_t)h * LSEQ + q) * LSEQ;
    const float* row = g_S + base;
    const float scale = 0.0883883476483184f;  // 1/sqrt(128)
    const float sv = sink[h];
    const int t = threadIdx.x;
    __shared__ float sred[8];

    float4 v[2];
    float lm = -3.0e38f;
#pragma unroll
    for (int i = 0; i < 2; i++) {
        const int k4 = t + i * 256;
        v[i] = *(const float4*)(row + k4 * 4);
        float* e = (float*)&v[i];
#pragma unroll
        for (int j = 0; j < 4; j++) {
            const int k = k4 * 4 + j;
            const bool masked = (q >= k) && (q < k + 1024);
            e[j] = masked ? -1e30f : e[j] * scale;
            lm = fmaxf(lm, e[j]);
        }
    }
    float wr = lm;
#pragma unroll
    for (int o = 16; o; o >>= 1) wr = fmaxf(wr, __shfl_xor_sync(0xffffffffu, wr, o));
    if ((t & 31) == 0) sred[t >> 5] = wr;
    __syncthreads();
    float gm = sred[0];
#pragma unroll
    for (int w = 1; w < 8; w++) gm = fmaxf(gm, sred[w]);
    const float m = fmaxf(gm, sv);
    __syncthreads();

    float ls = 0.f;
#pragma unroll
    for (int i = 0; i < 2; i++) {
        float* e = (float*)&v[i];
#pragma unroll
        for (int j = 0; j < 4; j++) {
            e[j] = expf(e[j] - m);
            ls += e[j];
        }
    }
    float ws = ls;
#pragma unroll
    for (int o = 16; o; o >>= 1) ws += __shfl_xor_sync(0xffffffffu, ws, o);
    if ((t & 31) == 0) sred[t >> 5] = ws;
    __syncthreads();
    float gs = 0.f;
#pragma unroll
    for (int w = 0; w < 8; w++) gs += sred[w];
    const float inv = 1.0f / (gs + expf(sv - m));

#pragma unroll
    for (int i = 0; i < 2; i++) {
        const int k4 = t + i * 256;
        float* e = (float*)&v[i];
        __nv_bfloat16 hh[4], ll[4];
#pragma unroll
        for (int j = 0; j < 4; j++) {
            const float w = e[j] * inv;
            hh[j] = __float2bfloat16(w);
            ll[j] = __float2bfloat16(w - __bfloat162float(hh[j]));
        }
        *(uint2*)(g_Shi + base + k4 * 4) = *(uint2*)hh;
        *(uint2*)(g_Slo + base + k4 * 4) = *(uint2*)ll;
    }
}

// ---------------- launch ----------------
extern "C" void kernel_launch(void* const* d_in, const int* in_sizes, int n_in,
                              void* d_out, int out_size)
{
    (void)in_sizes; (void)n_in; (void)out_size;
    const float* x    = (const float*)d_in[0];
    const float* Wqkv = (const float*)d_in[1];
    const float* Wo   = (const float*)d_in[2];
    const float* s    = (const float*)d_in[3];
    float* out = (float*)d_out;

    cudaFuncSetAttribute(gemm_mma<0>, cudaFuncAttributeMaxDynamicSharedMemorySize, GSMEM);
    cudaFuncSetAttribute(gemm_mma<1>, cudaFuncAttributeMaxDynamicSharedMemorySize, GSMEM);

    float *proj, *S;
    __nv_bfloat16 *xhi, *xlo, *Qhi, *Qlo, *Khi, *Klo, *VThi, *VTlo;
    __nv_bfloat16 *WqT_h, *WqT_l, *WoT_h, *WoT_l, *Shi, *Slo, *AOhi, *AOlo;
    cudaGetSymbolAddress((void**)&proj, g_proj);
    cudaGetSymbolAddress((void**)&S, g_S);
    cudaGetSymbolAddress((void**)&xhi, g_xhi);
    cudaGetSymbolAddress((void**)&xlo, g_xlo);
    cudaGetSymbolAddress((void**)&Qhi, g_Qhi);
    cudaGetSymbolAddress((void**)&Qlo, g_Qlo);
    cudaGetSymbolAddress((void**)&Khi, g_Khi);
    cudaGetSymbolAddress((void**)&Klo, g_Klo);
    cudaGetSymbolAddress((void**)&VThi, g_VThi);
    cudaGetSymbolAddress((void**)&VTlo, g_VTlo);
    cudaGetSymbolAddress((void**)&WqT_h, g_WqkvT_hi);
    cudaGetSymbolAddress((void**)&WqT_l, g_WqkvT_lo);
    cudaGetSymbolAddress((void**)&WoT_h, g_WoT_hi);
    cudaGetSymbolAddress((void**)&WoT_l, g_WoT_lo);
    cudaGetSymbolAddress((void**)&Shi, g_Shi);
    cudaGetSymbolAddress((void**)&Slo, g_Slo);
    cudaGetSymbolAddress((void**)&AOhi, g_AOhi);
    cudaGetSymbolAddress((void**)&AOlo, g_AOlo);

    // 0) operand prep
    split_kernel<<<(LSEQ * DMODEL / 4 + 255) / 256, 256>>>(x, xhi, xlo, LSEQ * DMODEL / 4);
    transpose_convert<<<dim3(QKVDIM / 32, DMODEL / 32, 1), 256>>>(
        Wqkv, WqT_h, WqT_l, QKVDIM, DMODEL, 0L, 0L);
    transpose_convert<<<dim3(DMODEL / 32, DMODEL / 32, 1), 256>>>(
        Wo, WoT_h, WoT_l, DMODEL, DMODEL, 0L, 0L);

    // 1) proj = x @ Wqkv  (M=2048, N=3072, K=2048)
    gemm_mma<0><<<dim3(QKVDIM / 128, LSEQ / 128, 1), 256, GSMEM>>>(
        xhi, xlo, WqT_h, WqT_l, proj, nullptr, nullptr,
        DMODEL, DMODEL, DMODEL, QKVDIM, 0L, 0L, 1, 0L);

    // 2) RoPE -> Q/K hi/lo ; V transpose -> VT hi/lo
    rope_split_kernel<<<LSEQ, 256>>>();
    transpose_convert<<<dim3(HD / 32, LSEQ / 32, HKV), 256>>>(
        proj + (HQ + HKV) * HD, VThi, VTlo, QKVDIM, LSEQ, (long)HD, (long)HD * LSEQ);

    // 3) S[h] = Q[h] @ K[h/4]^T  (M=2048, N=2048, K=128) x16
    gemm_mma<0><<<dim3(LSEQ / 128, LSEQ / 128, HQ), 256, GSMEM>>>(
        Qhi, Qlo, Khi, Klo, S, nullptr, nullptr,
        HD, HD, HD, LSEQ, (long)LSEQ * HD, (long)LSEQ * HD, 4, (long)LSEQ * LSEQ);

    // 4) masked softmax + sink -> S hi/lo
    softmax_kernel<<<dim3(LSEQ, HQ), 256>>>(s);

    // 5) AO[:, h*128:] = W[h] @ V[h/4]  (M=2048, N=128, K=2048) x16, split epilogue
    gemm_mma<1><<<dim3(1, LSEQ / 128, HQ), 256, GSMEM>>>(
        Shi, Slo, VThi, VTlo, nullptr, AOhi, AOlo,
        LSEQ, LSEQ, LSEQ, DMODEL, (long)LSEQ * LSEQ, (long)HD * LSEQ, 4, (long)HD);

    // 6) out = AO @ Wo  (M=2048, N=2048, K=2048)
    gemm_mma<0><<<dim3(DMODEL / 128, LSEQ / 128, 1), 256, GSMEM>>>(
        AOhi, AOlo, WoT_h, WoT_l, out, nullptr, nullptr,
        DMODEL, DMODEL, DMODEL, DMODEL, 0L, 0L, 1, 0L);
}